// round 10
// baseline (speedup 1.0000x reference)
#include <cuda_runtime.h>
#include <cuda_bf16.h>

#define BATCH 8
#define NPATCH 1024
#define G 32
#define IMG 512
#define CH_STRIDE (IMG * IMG)
#define NGROUPS (BATCH * NPATCH)          // 8192: one patch per work unit
#define NTHREADS 128                      // 4 independent warp-workers
#define GRID (148 * 8)                    // persistent, 8 blocks/SM

typedef unsigned long long u64;

union F4U { float4 f; u64 u[2]; };

__device__ unsigned int g_counter = 0;
__device__ unsigned int g_done    = 0;

__device__ __forceinline__ u64 pack2(float lo, float hi) {
    u64 r; asm("mov.b64 %0, {%1, %2};" : "=l"(r) : "f"(lo), "f"(hi)); return r;
}
__device__ __forceinline__ void unpack2(u64 v, float& lo, float& hi) {
    asm("mov.b64 {%0, %1}, %2;" : "=f"(lo), "=f"(hi) : "l"(v));
}
__device__ __forceinline__ u64 add2(u64 a, u64 b) {
    u64 d; asm("add.rn.f32x2 %0, %1, %2;" : "=l"(d) : "l"(a), "l"(b)); return d;
}
__device__ __forceinline__ u64 fma2(u64 a, u64 b, u64 c) {
    u64 d; asm("fma.rn.f32x2 %0, %1, %2, %3;" : "=l"(d) : "l"(a), "l"(b), "l"(c)); return d;
}
__device__ __forceinline__ float ex2f(float x) {
    float y; asm("ex2.approx.f32 %0, %1;" : "=f"(y) : "f"(x)); return y;
}
__device__ __forceinline__ float fast_sigmoid(float x) {
    return 1.0f / (1.0f + __expf(-x));
}

__global__ __launch_bounds__(NTHREADS, 8)
void splat_kernel(const float* __restrict__ xyz,
                  const float* __restrict__ chol,
                  const float* __restrict__ color,
                  const float* __restrict__ opac,
                  float* __restrict__ out)
{
    // Per-warp private slice of per-gaussian constants (2 float4 each):
    //  [0] = {-mx, my, cA, cB}   [1] = {cC, o0, o1, o2}
    __shared__ float4 sg[NTHREADS / 32][G][2];

    const int tid  = threadIdx.x;
    const int lane = tid & 31;
    const int wid  = tid >> 5;           // warp worker id 0..3
    const int row  = lane >> 1;          // 0..15
    const int half = lane & 1;           // 0..1
    const float py = (float)row + 0.5f;
    const float xb = (float)(half * 8) + 0.5f;

    const u64 px0  = pack2(xb, xb + 1.0f);
    const u64 two2 = pack2(2.0f, 2.0f);

    float4 (*my_sg)[2] = sg[wid];

    for (;;) {
        // ---- warp-private work grab ----
        unsigned int grp;
        if (lane == 0) grp = atomicAdd(&g_counter, 1u);
        grp = __shfl_sync(0xffffffffu, grp, 0);
        if (grp >= NGROUPS) break;

        // ---- preprocess: lane g -> gaussian g of this patch ----
        {
            const long gi = (long)grp * G + lane;
            const float x0 = xyz[gi * 2 + 0];
            const float x1 = xyz[gi * 2 + 1];
            const float c0 = chol[gi * 3 + 0];
            const float c1 = chol[gi * 3 + 1];
            const float c2 = chol[gi * 3 + 2];
            const float k0 = color[gi * 3 + 0];
            const float k1 = color[gi * 3 + 1];
            const float k2 = color[gi * 3 + 2];
            const float po = opac[gi];

            const float mx = 16.0f * fast_sigmoid(x0);
            const float my = 16.0f * fast_sigmoid(x1);

            const float l0 = fabsf(c0) + 0.5f;
            const float l1 = c1;
            const float l2 = fabsf(c2) + 0.5f;
            const float s00 = l0 * l0;
            const float s01 = l0 * l1;
            const float s11 = l1 * l1 + l2 * l2;
            const float inv = 1.0f / (s00 * (l2 * l2));  // 1/det, det=(l0*l2)^2

            const float L2E = 1.4426950408889634f;
            const float cA = -0.5f * L2E * (s11 * inv);
            const float cB =         L2E * (s01 * inv);
            const float cC = -0.5f * L2E * (s00 * inv);

            const float a = fast_sigmoid(po);
            my_sg[lane][0] = make_float4(-mx, my, cA, cB);
            my_sg[lane][1] = make_float4(cC, a * k0, a * k1, a * k2);
        }
        __syncwarp();

        // ---- rasterize: 1 warp = 1 patch, 1 thread = 8-px half-row ----
        u64 acc0[4] = {0,0,0,0};
        u64 acc1[4] = {0,0,0,0};
        u64 acc2[4] = {0,0,0,0};

        const float4* gp = &my_sg[0][0];

#pragma unroll 4
        for (int g = 0; g < G; ++g) {
            const float4 q0 = gp[2*g + 0];
            const float4 q1 = gp[2*g + 1];

            const float dy  = py - q0.y;
            const float bdy = q0.w * dy;          // cB*dy (scalar)
            const float t2  = (q1.x * dy) * dy;   // cC*dy^2 (scalar)

            const u64 mxp  = pack2(q0.x, q0.x);   // {-mx,-mx}
            const u64 cAp  = pack2(q0.z, q0.z);
            const u64 bdyp = pack2(bdy, bdy);
            const u64 t2p  = pack2(t2, t2);

            // Phase 1: all dx pairs (short serial add chain)
            u64 dxp[4];
            dxp[0] = add2(px0, mxp);
            dxp[1] = add2(dxp[0], two2);
            dxp[2] = add2(dxp[1], two2);
            dxp[3] = add2(dxp[2], two2);

            // Phase 2: all quadratics
            u64 p2[4];
#pragma unroll
            for (int j = 0; j < 4; ++j) {
                const u64 u2 = fma2(cAp, dxp[j], bdyp);  // cA*dx + cB*dy
                p2[j] = fma2(dxp[j], u2, t2p);           // exponent (log2), <= 0
            }

            // Phase 3: batch of 8 independent EX2s
            u64 e2[4];
#pragma unroll
            for (int j = 0; j < 4; ++j) {
                float a0, a1; unpack2(p2[j], a0, a1);
                e2[j] = pack2(ex2f(a0), ex2f(a1));
            }

            // Phase 4: accumulate 3 channels
            const u64 o0p = pack2(q1.y, q1.y);
            const u64 o1p = pack2(q1.z, q1.z);
            const u64 o2p = pack2(q1.w, q1.w);
#pragma unroll
            for (int j = 0; j < 4; ++j) {
                acc0[j] = fma2(e2[j], o0p, acc0[j]);
                acc1[j] = fma2(e2[j], o1p, acc1[j]);
                acc2[j] = fma2(e2[j], o2p, acc2[j]);
            }
        }

        // ---- store: [B,3,512,512] ----
        const int b  = grp >> 10;
        const int p  = grp & 1023;
        const int Y  = (p >> 5) * 16 + row;
        const int X  = (p & 31) * 16 + half * 8;
        float* o = out + (long)b * 3 * CH_STRIDE + (long)Y * IMG + X;

        F4U w;
        w.u[0] = acc0[0]; w.u[1] = acc0[1]; *(float4*)(o)                     = w.f;
        w.u[0] = acc0[2]; w.u[1] = acc0[3]; *(float4*)(o + 4)                 = w.f;
        w.u[0] = acc1[0]; w.u[1] = acc1[1]; *(float4*)(o + CH_STRIDE)         = w.f;
        w.u[0] = acc1[2]; w.u[1] = acc1[3]; *(float4*)(o + CH_STRIDE + 4)     = w.f;
        w.u[0] = acc2[0]; w.u[1] = acc2[1]; *(float4*)(o + 2 * CH_STRIDE)     = w.f;
        w.u[0] = acc2[2]; w.u[1] = acc2[3]; *(float4*)(o + 2 * CH_STRIDE + 4) = w.f;

        __syncwarp();   // all lanes done reading smem before next preprocess
    }

    // ---- last block to finish resets the queue for the next graph replay ----
    __syncthreads();
    if (tid == 0) {
        __threadfence();
        if (atomicAdd(&g_done, 1u) == GRID - 1u) {
            g_counter = 0;
            g_done    = 0;
        }
    }
}

extern "C" void kernel_launch(void* const* d_in, const int* in_sizes, int n_in,
                              void* d_out, int out_size)
{
    const float* xyz   = (const float*)d_in[0];
    const float* chol  = (const float*)d_in[1];
    const float* color = (const float*)d_in[2];
    const float* opac  = (const float*)d_in[3];
    float* out = (float*)d_out;

    splat_kernel<<<GRID, NTHREADS>>>(xyz, chol, color, opac, out);
}

// round 11
// speedup vs baseline: 1.0757x; 1.0757x over previous
#include <cuda_runtime.h>
#include <cuda_bf16.h>

#define BATCH 8
#define NPATCH 1024
#define G 32
#define IMG 512
#define CH_STRIDE (IMG * IMG)
#define PPB 4                             // patches per group (1 warp per patch)
#define NGROUPS (BATCH * NPATCH / PPB)    // 2048
#define NTHREADS 128
#define GRID (148 * 8)                    // persistent, 8 blocks/SM

typedef unsigned long long u64;

union F4U { float4 f; u64 u[2]; };

__device__ unsigned int g_counter = 0;
__device__ unsigned int g_done    = 0;

__device__ __forceinline__ u64 pack2(float lo, float hi) {
    u64 r; asm("mov.b64 %0, {%1, %2};" : "=l"(r) : "f"(lo), "f"(hi)); return r;
}
__device__ __forceinline__ void unpack2(u64 v, float& lo, float& hi) {
    asm("mov.b64 {%0, %1}, %2;" : "=f"(lo), "=f"(hi) : "l"(v));
}
__device__ __forceinline__ u64 add2(u64 a, u64 b) {
    u64 d; asm("add.rn.f32x2 %0, %1, %2;" : "=l"(d) : "l"(a), "l"(b)); return d;
}
__device__ __forceinline__ u64 fma2(u64 a, u64 b, u64 c) {
    u64 d; asm("fma.rn.f32x2 %0, %1, %2, %3;" : "=l"(d) : "l"(a), "l"(b), "l"(c)); return d;
}
__device__ __forceinline__ float ex2f(float x) {
    float y; asm("ex2.approx.f32 %0, %1;" : "=f"(y) : "f"(x)); return y;
}
__device__ __forceinline__ float fast_sigmoid(float x) {
    return 1.0f / (1.0f + __expf(-x));
}

__global__ __launch_bounds__(NTHREADS, 8)
void splat_kernel(const float* __restrict__ xyz,
                  const float* __restrict__ chol,
                  const float* __restrict__ color,
                  const float* __restrict__ opac,
                  float* __restrict__ out)
{
    // Compact per-gaussian constants (2 float4 each):
    //  [0] = {-mx, my, cA, cB}   [1] = {cC, o0, o1, o2}
    __shared__ float4 sg[PPB * G][2];
    __shared__ int s_grp;

    const int tid  = threadIdx.x;
    const int lane = tid & 31;
    const int lp   = tid >> 5;          // warp = local patch 0..3
    const int row  = lane >> 1;         // 0..15
    const int half = lane & 1;          // 0..1
    const float py = (float)row + 0.5f;
    const float xb = (float)(half * 8) + 0.5f;

    // 4 independent pixel-pair x constants (no serial dx chain)
    u64 pxp[4];
#pragma unroll
    for (int j = 0; j < 4; ++j)
        pxp[j] = pack2(xb + (float)(2 * j), xb + (float)(2 * j + 1));

    for (;;) {
        // ---- grab next work group ----
        if (tid == 0) s_grp = (int)atomicAdd(&g_counter, 1u);
        __syncthreads();                 // also protects smem reuse
        const int grp = s_grp;
        if (grp >= NGROUPS) break;

        // ---- preprocess: 128 threads -> 128 gaussians (4 patches x 32) ----
        {
            const long gi = (long)grp * (PPB * G) + tid;
            const float x0 = xyz[gi * 2 + 0];
            const float x1 = xyz[gi * 2 + 1];
            const float c0 = chol[gi * 3 + 0];
            const float c1 = chol[gi * 3 + 1];
            const float c2 = chol[gi * 3 + 2];
            const float k0 = color[gi * 3 + 0];
            const float k1 = color[gi * 3 + 1];
            const float k2 = color[gi * 3 + 2];
            const float po = opac[gi];

            const float mx = 16.0f * fast_sigmoid(x0);
            const float my = 16.0f * fast_sigmoid(x1);

            const float l0 = fabsf(c0) + 0.5f;
            const float l1 = c1;
            const float l2 = fabsf(c2) + 0.5f;
            const float s00 = l0 * l0;
            const float s01 = l0 * l1;
            const float s11 = l1 * l1 + l2 * l2;
            const float inv = 1.0f / (s00 * (l2 * l2));  // 1/det, det=(l0*l2)^2

            const float L2E = 1.4426950408889634f;
            const float cA = -0.5f * L2E * (s11 * inv);
            const float cB =         L2E * (s01 * inv);
            const float cC = -0.5f * L2E * (s00 * inv);

            const float a = fast_sigmoid(po);
            sg[tid][0] = make_float4(-mx, my, cA, cB);
            sg[tid][1] = make_float4(cC, a * k0, a * k1, a * k2);
        }
        __syncthreads();

        // ---- rasterize: 1 warp = 1 patch, 1 thread = 8-px half-row ----
        u64 acc0[4] = {0,0,0,0};
        u64 acc1[4] = {0,0,0,0};
        u64 acc2[4] = {0,0,0,0};

        const float4* gp = &sg[lp * G][0];

#pragma unroll 8
        for (int g = 0; g < G; ++g) {
            const float4 q0 = gp[2*g + 0];
            const float4 q1 = gp[2*g + 1];

            const float dy  = py - q0.y;
            const float bdy = q0.w * dy;          // cB*dy (scalar)
            const float t2  = (q1.x * dy) * dy;   // cC*dy^2 (scalar)

            const u64 mxp  = pack2(q0.x, q0.x);   // {-mx,-mx}
            const u64 cAp  = pack2(q0.z, q0.z);
            const u64 bdyp = pack2(bdy, bdy);
            const u64 t2p  = pack2(t2, t2);

            // Phase 1: all dx pairs, fully independent
            u64 dxp[4];
#pragma unroll
            for (int j = 0; j < 4; ++j)
                dxp[j] = add2(pxp[j], mxp);

            // Phase 2: all quadratics (independent given dx pairs)
            u64 p2[4];
#pragma unroll
            for (int j = 0; j < 4; ++j) {
                const u64 u2 = fma2(cAp, dxp[j], bdyp);  // cA*dx + cB*dy
                p2[j] = fma2(dxp[j], u2, t2p);           // exponent (log2), <= 0
            }

            // Phase 3: batch of 8 independent EX2s (fills the MUFU pipeline)
            u64 e2[4];
#pragma unroll
            for (int j = 0; j < 4; ++j) {
                float a0, a1; unpack2(p2[j], a0, a1);
                e2[j] = pack2(ex2f(a0), ex2f(a1));
            }

            // Phase 4: accumulate 3 channels
            const u64 o0p = pack2(q1.y, q1.y);
            const u64 o1p = pack2(q1.z, q1.z);
            const u64 o2p = pack2(q1.w, q1.w);
#pragma unroll
            for (int j = 0; j < 4; ++j) {
                acc0[j] = fma2(e2[j], o0p, acc0[j]);
                acc1[j] = fma2(e2[j], o1p, acc1[j]);
                acc2[j] = fma2(e2[j], o2p, acc2[j]);
            }
        }

        // ---- store: [B,3,512,512] ----
        const int wp = grp * PPB + lp;
        const int b  = wp >> 10;
        const int p  = wp & 1023;
        const int Y  = (p >> 5) * 16 + row;
        const int X  = (p & 31) * 16 + half * 8;
        float* o = out + (long)b * 3 * CH_STRIDE + (long)Y * IMG + X;

        F4U w;
        w.u[0] = acc0[0]; w.u[1] = acc0[1]; *(float4*)(o)                     = w.f;
        w.u[0] = acc0[2]; w.u[1] = acc0[3]; *(float4*)(o + 4)                 = w.f;
        w.u[0] = acc1[0]; w.u[1] = acc1[1]; *(float4*)(o + CH_STRIDE)         = w.f;
        w.u[0] = acc1[2]; w.u[1] = acc1[3]; *(float4*)(o + CH_STRIDE + 4)     = w.f;
        w.u[0] = acc2[0]; w.u[1] = acc2[1]; *(float4*)(o + 2 * CH_STRIDE)     = w.f;
        w.u[0] = acc2[2]; w.u[1] = acc2[3]; *(float4*)(o + 2 * CH_STRIDE + 4) = w.f;
    }

    // ---- last block to finish resets the queue for the next graph replay ----
    __syncthreads();
    if (tid == 0) {
        __threadfence();
        if (atomicAdd(&g_done, 1u) == GRID - 1u) {
            g_counter = 0;
            g_done    = 0;
        }
    }
}

extern "C" void kernel_launch(void* const* d_in, const int* in_sizes, int n_in,
                              void* d_out, int out_size)
{
    const float* xyz   = (const float*)d_in[0];
    const float* chol  = (const float*)d_in[1];
    const float* color = (const float*)d_in[2];
    const float* opac  = (const float*)d_in[3];
    float* out = (float*)d_out;

    splat_kernel<<<GRID, NTHREADS>>>(xyz, chol, color, opac, out);
}